// round 7
// baseline (speedup 1.0000x reference)
#include <cuda_runtime.h>
#include <cuda_bf16.h>
#include <cstdint>

// Flash-style SDPA via portable mma.sync (bf16 HMMA), sm_103-safe PTX.
// B=4,H=16,S=2048,D=64 fp32. Split-bf16 3-term MMAs for both GEMMs.
// R7: BM=64, 128 threads/CTA -> 2 CTAs/SM so one CTA's pack/softmax
// overlaps the other CTA's HMMA chains. exp via ex2.approx with log2e
// folded into the Q scale.

#define S_LEN   2048
#define NHEADS  64
#define DIM     64
#define BM      64
#define BN      128
#define NKT     (S_LEN / BN)   // 16
#define NTH     128

// smem: KH[2048] KL[2048] VH[2048] VL[2048] uint2 = 4 * 16 KB
#define SM_KH 0
#define SM_KL 16384
#define SM_VH 32768
#define SM_VL 49152
#define SM_BYTES 65536

#define QSCALE (0.125f * 1.4426950408889634f)   // 1/sqrt(64) * log2(e)

__device__ __forceinline__ float ex2(float x) {
    float y;
    asm("ex2.approx.f32 %0, %1;" : "=f"(y) : "f"(x));
    return y;
}

__device__ __forceinline__ void split2(float a, float b, uint32_t& hi, uint32_t& lo) {
    __nv_bfloat162 h = __floats2bfloat162_rn(a, b);
    float ra = a - __bfloat162float(h.x);
    float rb = b - __bfloat162float(h.y);
    __nv_bfloat162 l = __floats2bfloat162_rn(ra, rb);
    hi = *reinterpret_cast<uint32_t*>(&h);
    lo = *reinterpret_cast<uint32_t*>(&l);
}

__device__ __forceinline__ void mma16816(float* c, const uint32_t* a,
                                         uint32_t b0, uint32_t b1) {
    asm volatile(
        "mma.sync.aligned.m16n8k16.row.col.f32.bf16.bf16.f32 "
        "{%0,%1,%2,%3}, {%4,%5,%6,%7}, {%8,%9}, {%0,%1,%2,%3};"
        : "+f"(c[0]), "+f"(c[1]), "+f"(c[2]), "+f"(c[3])
        : "r"(a[0]), "r"(a[1]), "r"(a[2]), "r"(a[3]), "r"(b0), "r"(b1));
}

__global__ __launch_bounds__(NTH, 2)
void sdpa_mma_kernel(const float* __restrict__ qg, const float* __restrict__ kg,
                     const float* __restrict__ vg, float* __restrict__ og) {
    extern __shared__ __align__(16) char smem[];
    uint2* KH = (uint2*)(smem + SM_KH);
    uint2* KL = (uint2*)(smem + SM_KL);
    uint2* VH = (uint2*)(smem + SM_VH);
    uint2* VL = (uint2*)(smem + SM_VL);

    const int tid  = threadIdx.x;
    const int warp = tid >> 5;
    const int lane = tid & 31;
    const int g    = lane >> 2;     // 0..7  row-in-fragment group
    const int tig  = lane & 3;      // 0..3  thread-in-group

    const int head = blockIdx.y;
    const int mt   = blockIdx.x;

    const float* qt = qg + ((size_t)head * S_LEN + (size_t)mt * BM) * DIM;
    const float* kb = kg + (size_t)head * S_LEN * DIM;
    const float* vb = vg + (size_t)head * S_LEN * DIM;
    float*       ot = og + ((size_t)head * S_LEN + (size_t)mt * BM) * DIM;

    // ---- Q fragments, register-resident, scale = 1/sqrt(D) * log2(e) ----
    uint32_t qh[4][4], ql[4][4];
    {
        const float* qr = qt + (warp * 16 + g) * DIM + 2 * tig;
        #pragma unroll
        for (int ks = 0; ks < 4; ks++) {
            float2 u0 = *(const float2*)(qr + ks * 16);
            float2 u1 = *(const float2*)(qr + ks * 16 + 8);
            float2 u2 = *(const float2*)(qr + ks * 16 + 8 * DIM);
            float2 u3 = *(const float2*)(qr + ks * 16 + 8 * DIM + 8);
            split2(QSCALE * u0.x, QSCALE * u0.y, qh[ks][0], ql[ks][0]);
            split2(QSCALE * u2.x, QSCALE * u2.y, qh[ks][1], ql[ks][1]);
            split2(QSCALE * u1.x, QSCALE * u1.y, qh[ks][2], ql[ks][2]);
            split2(QSCALE * u3.x, QSCALE * u3.y, qh[ks][3], ql[ks][3]);
        }
    }

    float o[8][4];
    #pragma unroll
    for (int i = 0; i < 8; i++)
        #pragma unroll
        for (int j = 0; j < 4; j++) o[i][j] = 0.0f;
    float rs0 = 0.0f, rs1 = 0.0f;   // row sums for rows g and g+8

    for (int t = 0; t < NKT; t++) {
        __syncthreads();   // previous tile's fragment reads complete

        // ---- pack K tile into B-frag order: pos=(nt*4+ks)*32+lane ----
        {
            const float* kt = kb + (size_t)t * BN * DIM;
            #pragma unroll
            for (int i = 0; i < 16; i++) {
                int pos = i * NTH + tid;
                int ln = pos & 31, ks = (pos >> 5) & 3, nt = pos >> 7;
                int gg = ln >> 2, tt = ln & 3;
                const float* src = kt + (nt * 8 + gg) * DIM + ks * 16 + 2 * tt;
                float2 x0 = *(const float2*)src;        // k = 2t, 2t+1
                float2 x1 = *(const float2*)(src + 8);  // k = 2t+8, 2t+9
                uint32_t h0, l0, h1, l1;
                split2(x0.x, x0.y, h0, l0);
                split2(x1.x, x1.y, h1, l1);
                KH[pos] = make_uint2(h0, h1);
                KL[pos] = make_uint2(l0, l1);
            }
        }
        // ---- pack V tile: pos=(nt*8+ks)*32+lane, B[k=key][n=dim] ----
        {
            const float* vt = vb + (size_t)t * BN * DIM;
            #pragma unroll
            for (int i = 0; i < 16; i++) {
                int pos = i * NTH + tid;
                int ln = pos & 31, ks = (pos >> 5) & 7, nt = pos >> 8;
                int gg = ln >> 2, tt = ln & 3;
                const float* src = vt + (ks * 16 + 2 * tt) * DIM + nt * 8 + gg;
                float y0 = src[0];
                float y1 = src[DIM];
                float y2 = src[8 * DIM];
                float y3 = src[9 * DIM];
                uint32_t h0, l0, h1, l1;
                split2(y0, y1, h0, l0);
                split2(y2, y3, h1, l1);
                VH[pos] = make_uint2(h0, h1);
                VL[pos] = make_uint2(l0, l1);
            }
        }
        __syncthreads();   // fragments ready

        // ---- GEMM1: S[64x128] = Qh Kh + Qh Kl + Ql Kh ----
        float s[16][4];
        #pragma unroll
        for (int nt = 0; nt < 16; nt++) {
            s[nt][0] = s[nt][1] = s[nt][2] = s[nt][3] = 0.0f;
            #pragma unroll
            for (int ks = 0; ks < 4; ks++) {
                uint2 bh = KH[(nt * 4 + ks) * 32 + lane];
                uint2 bl = KL[(nt * 4 + ks) * 32 + lane];
                mma16816(s[nt], qh[ks], bh.x, bh.y);
                mma16816(s[nt], qh[ks], bl.x, bl.y);
                mma16816(s[nt], ql[ks], bh.x, bh.y);
            }
        }

        // ---- 2^s + rowsum + split to GEMM2 A-frags (pure registers) ----
        uint32_t pha[8][4], pla[8][4];
        #pragma unroll
        for (int s8 = 0; s8 < 8; s8++) {
            float p00 = ex2(s[2 * s8][0]),     p01 = ex2(s[2 * s8][1]);
            float p02 = ex2(s[2 * s8][2]),     p03 = ex2(s[2 * s8][3]);
            float p10 = ex2(s[2 * s8 + 1][0]), p11 = ex2(s[2 * s8 + 1][1]);
            float p12 = ex2(s[2 * s8 + 1][2]), p13 = ex2(s[2 * s8 + 1][3]);
            rs0 += (p00 + p01) + (p10 + p11);
            rs1 += (p02 + p03) + (p12 + p13);
            split2(p00, p01, pha[s8][0], pla[s8][0]);
            split2(p02, p03, pha[s8][1], pla[s8][1]);
            split2(p10, p11, pha[s8][2], pla[s8][2]);
            split2(p12, p13, pha[s8][3], pla[s8][3]);
        }

        // ---- GEMM2: O += Ph Vh + Pl Vh + Ph Vl ----
        #pragma unroll
        for (int nt = 0; nt < 8; nt++) {
            #pragma unroll
            for (int ks = 0; ks < 8; ks++) {
                uint2 vh = VH[(nt * 8 + ks) * 32 + lane];
                uint2 vl = VL[(nt * 8 + ks) * 32 + lane];
                mma16816(o[nt], pha[ks], vh.x, vh.y);
                mma16816(o[nt], pla[ks], vh.x, vh.y);
                mma16816(o[nt], pha[ks], vl.x, vl.y);
            }
        }
    }

    // ---- epilogue: reduce row sums across the quad, divide, store ----
    rs0 += __shfl_xor_sync(0xffffffffu, rs0, 1);
    rs0 += __shfl_xor_sync(0xffffffffu, rs0, 2);
    rs1 += __shfl_xor_sync(0xffffffffu, rs1, 1);
    rs1 += __shfl_xor_sync(0xffffffffu, rs1, 2);
    const float inv0 = 1.0f / rs0;
    const float inv1 = 1.0f / rs1;

    float* orow0 = ot + (warp * 16 + g) * DIM + 2 * tig;
    float* orow1 = orow0 + 8 * DIM;
    #pragma unroll
    for (int nt = 0; nt < 8; nt++) {
        *(float2*)(orow0 + nt * 8) = make_float2(o[nt][0] * inv0, o[nt][1] * inv0);
        *(float2*)(orow1 + nt * 8) = make_float2(o[nt][2] * inv1, o[nt][3] * inv1);
    }
}

extern "C" void kernel_launch(void* const* d_in, const int* in_sizes, int n_in,
                              void* d_out, int out_size) {
    const float* q = (const float*)d_in[0];
    const float* k = (const float*)d_in[1];
    const float* v = (const float*)d_in[2];
    float* o = (float*)d_out;

    cudaFuncSetAttribute(sdpa_mma_kernel,
                         cudaFuncAttributeMaxDynamicSharedMemorySize, SM_BYTES);
    dim3 grid(S_LEN / BM, NHEADS);   // (32, 64)
    sdpa_mma_kernel<<<grid, NTH, SM_BYTES>>>(q, k, v, o);
}

// round 9
// speedup vs baseline: 1.1367x; 1.1367x over previous
#include <cuda_runtime.h>
#include <cuda_bf16.h>
#include <cstdint>

// Flash-style SDPA via portable mma.sync (bf16 HMMA), sm_103-safe PTX.
// B=4,H=16,S=2048,D=64 fp32. Split-bf16 3-term MMAs for both GEMMs.
// R8: R6 config (BM=128, 256 thr) + cp.async double-buffered raw staging
// (gmem latency hidden under MMA) + interleaved uint4 fragments (LDS.128)
// + ex2.approx with log2e folded into the Q scale.

#define S_LEN   2048
#define NHEADS  64
#define DIM     64
#define BM      128
#define BN      128
#define NKT     (S_LEN / BN)   // 16
#define NTH     256

#define RAW_STRIDE 68                      // floats per staged row (pad 64->68)
#define RAW_TILE   (128 * RAW_STRIDE * 4)  // bytes per staged K or V tile (34816)

// smem layout (bytes)
#define SM_KF  0                    // 2048 x uint4 (kh0,kh1,kl0,kl1) = 32 KB
#define SM_VF  32768                // 2048 x uint4 (vh0,vh1,vl0,vl1) = 32 KB
#define SM_RAW 65536                // 2 buffers x (K tile + V tile) raw fp32
#define SM_BYTES (65536 + 4 * RAW_TILE)   // 204800

#define QSCALE (0.125f * 1.4426950408889634f)   // 1/sqrt(64) * log2(e)

__device__ __forceinline__ float ex2(float x) {
    float y;
    asm("ex2.approx.f32 %0, %1;" : "=f"(y) : "f"(x));
    return y;
}

__device__ __forceinline__ uint32_t smem_u32(const void* p) {
    uint32_t a;
    asm("{ .reg .u64 t; cvta.to.shared.u64 t, %1; cvt.u32.u64 %0, t; }"
        : "=r"(a) : "l"(p));
    return a;
}

__device__ __forceinline__ void cp16(uint32_t saddr, const void* gaddr) {
    asm volatile("cp.async.ca.shared.global [%0], [%1], 16;"
                 :: "r"(saddr), "l"(gaddr) : "memory");
}
#define CP_COMMIT() asm volatile("cp.async.commit_group;" ::: "memory")
#define CP_WAIT0()  asm volatile("cp.async.wait_group 0;" ::: "memory")

__device__ __forceinline__ void split2(float a, float b, uint32_t& hi, uint32_t& lo) {
    __nv_bfloat162 h = __floats2bfloat162_rn(a, b);
    float ra = a - __bfloat162float(h.x);
    float rb = b - __bfloat162float(h.y);
    __nv_bfloat162 l = __floats2bfloat162_rn(ra, rb);
    hi = *reinterpret_cast<uint32_t*>(&h);
    lo = *reinterpret_cast<uint32_t*>(&l);
}

__device__ __forceinline__ void mma16816(float* c, const uint32_t* a,
                                         uint32_t b0, uint32_t b1) {
    asm volatile(
        "mma.sync.aligned.m16n8k16.row.col.f32.bf16.bf16.f32 "
        "{%0,%1,%2,%3}, {%4,%5,%6,%7}, {%8,%9}, {%0,%1,%2,%3};"
        : "+f"(c[0]), "+f"(c[1]), "+f"(c[2]), "+f"(c[3])
        : "r"(a[0]), "r"(a[1]), "r"(a[2]), "r"(a[3]), "r"(b0), "r"(b1));
}

__global__ __launch_bounds__(NTH, 1)
void sdpa_mma_kernel(const float* __restrict__ qg, const float* __restrict__ kg,
                     const float* __restrict__ vg, float* __restrict__ og) {
    extern __shared__ __align__(16) char smem[];
    uint4* KF = (uint4*)(smem + SM_KF);
    uint4* VF = (uint4*)(smem + SM_VF);

    const int tid  = threadIdx.x;
    const int warp = tid >> 5;
    const int lane = tid & 31;
    const int g    = lane >> 2;
    const int tig  = lane & 3;

    const int head = blockIdx.y;
    const int mt   = blockIdx.x;

    const float* qt = qg + ((size_t)head * S_LEN + (size_t)mt * BM) * DIM;
    const float* kb = kg + (size_t)head * S_LEN * DIM;
    const float* vb = vg + (size_t)head * S_LEN * DIM;
    float*       ot = og + ((size_t)head * S_LEN + (size_t)mt * BM) * DIM;

    const uint32_t sb = smem_u32(smem);

    // ---- stage(t, buf): async copy raw K/V tile t into raw buffer ----
    auto stage = [&](int t, int buf) {
        const float* kt = kb + (size_t)t * BN * DIM;
        const float* vt = vb + (size_t)t * BN * DIM;
        uint32_t rbK = sb + SM_RAW + (uint32_t)buf * 2u * RAW_TILE;
        uint32_t rbV = rbK + RAW_TILE;
        #pragma unroll
        for (int i = 0; i < 16; i++) {
            int idx = i * NTH + tid;          // 0..4095
            int row = idx >> 4;               // 0..255 (uniform per i)
            int seg = idx & 15;               // 16B segment
            if (row < 128)
                cp16(rbK + (uint32_t)(row * (RAW_STRIDE * 4) + seg * 16),
                     kt + row * DIM + seg * 4);
            else
                cp16(rbV + (uint32_t)((row - 128) * (RAW_STRIDE * 4) + seg * 16),
                     vt + (row - 128) * DIM + seg * 4);
        }
        CP_COMMIT();
    };

    stage(0, 0);   // prefetch tile 0 while we build Q fragments

    // ---- Q fragments, register-resident, scale = 1/sqrt(D) * log2(e) ----
    uint32_t qh[4][4], ql[4][4];
    {
        const float* qr = qt + (warp * 16 + g) * DIM + 2 * tig;
        #pragma unroll
        for (int ks = 0; ks < 4; ks++) {
            float2 u0 = *(const float2*)(qr + ks * 16);
            float2 u1 = *(const float2*)(qr + ks * 16 + 8);
            float2 u2 = *(const float2*)(qr + ks * 16 + 8 * DIM);
            float2 u3 = *(const float2*)(qr + ks * 16 + 8 * DIM + 8);
            split2(QSCALE * u0.x, QSCALE * u0.y, qh[ks][0], ql[ks][0]);
            split2(QSCALE * u2.x, QSCALE * u2.y, qh[ks][1], ql[ks][1]);
            split2(QSCALE * u1.x, QSCALE * u1.y, qh[ks][2], ql[ks][2]);
            split2(QSCALE * u3.x, QSCALE * u3.y, qh[ks][3], ql[ks][3]);
        }
    }

    float o[8][4];
    #pragma unroll
    for (int i = 0; i < 8; i++)
        #pragma unroll
        for (int j = 0; j < 4; j++) o[i][j] = 0.0f;
    float rs0 = 0.0f, rs1 = 0.0f;

    for (int t = 0; t < NKT; t++) {
        CP_WAIT0();          // raw[t&1] landed
        __syncthreads();     // + everyone done reading frags of tile t-1

        const float* rawK = (const float*)(smem + SM_RAW + (t & 1) * 2 * RAW_TILE);
        const float* rawV = rawK + 128 * RAW_STRIDE;

        // ---- pack K frags from raw smem: pos=(nt*4+ks)*32+lane ----
        #pragma unroll
        for (int i = 0; i < 8; i++) {
            int pos = i * NTH + tid;
            int ln = pos & 31, ks = (pos >> 5) & 3, nt = pos >> 7;
            int gg = ln >> 2, tt = ln & 3;
            const float* src = rawK + (nt * 8 + gg) * RAW_STRIDE + ks * 16 + 2 * tt;
            float2 x0 = *(const float2*)src;
            float2 x1 = *(const float2*)(src + 8);
            uint32_t h0, l0, h1, l1;
            split2(x0.x, x0.y, h0, l0);
            split2(x1.x, x1.y, h1, l1);
            KF[pos] = make_uint4(h0, h1, l0, l1);
        }
        // ---- pack V frags: pos=(nt*8+ks)*32+lane ----
        #pragma unroll
        for (int i = 0; i < 8; i++) {
            int pos = i * NTH + tid;
            int ln = pos & 31, ks = (pos >> 5) & 7, nt = pos >> 8;
            int gg = ln >> 2, tt = ln & 3;
            const float* src = rawV + (ks * 16 + 2 * tt) * RAW_STRIDE + nt * 8 + gg;
            float y0 = src[0];
            float y1 = src[RAW_STRIDE];
            float y2 = src[8 * RAW_STRIDE];
            float y3 = src[9 * RAW_STRIDE];
            uint32_t h0, l0, h1, l1;
            split2(y0, y1, h0, l0);
            split2(y2, y3, h1, l1);
            VF[pos] = make_uint4(h0, h1, l0, l1);
        }
        __syncthreads();     // frags ready; raw[t&1] fully consumed

        if (t + 1 < NKT) stage(t + 1, (t + 1) & 1);   // overlaps MMA below

        // ---- GEMM1: S = Qh Kh + Qh Kl + Ql Kh ----
        float s[16][4];
        #pragma unroll
        for (int nt = 0; nt < 16; nt++) {
            s[nt][0] = s[nt][1] = s[nt][2] = s[nt][3] = 0.0f;
            #pragma unroll
            for (int ks = 0; ks < 4; ks++) {
                uint4 kf = KF[(nt * 4 + ks) * 32 + lane];
                mma16816(s[nt], qh[ks], kf.x, kf.y);
                mma16816(s[nt], qh[ks], kf.z, kf.w);
                mma16816(s[nt], ql[ks], kf.x, kf.y);
            }
        }

        // ---- 2^s + rowsum + split to GEMM2 A-frags (registers) ----
        uint32_t pha[8][4], pla[8][4];
        #pragma unroll
        for (int s8 = 0; s8 < 8; s8++) {
            float p00 = ex2(s[2 * s8][0]),     p01 = ex2(s[2 * s8][1]);
            float p02 = ex2(s[2 * s8][2]),     p03 = ex2(s[2 * s8][3]);
            float p10 = ex2(s[2 * s8 + 1][0]), p11 = ex2(s[2 * s8 + 1][1]);
            float p12 = ex2(s[2 * s8 + 1][2]), p13 = ex2(s[2 * s8 + 1][3]);
            rs0 += (p00 + p01) + (p10 + p11);
            rs1 += (p02 + p03) + (p12 + p13);
            split2(p00, p01, pha[s8][0], pla[s8][0]);
            split2(p02, p03, pha[s8][1], pla[s8][1]);
            split2(p10, p11, pha[s8][2], pla[s8][2]);
            split2(p12, p13, pha[s8][3], pla[s8][3]);
        }

        // ---- GEMM2: O += Ph Vh + Pl Vh + Ph Vl ----
        #pragma unroll
        for (int nt = 0; nt < 8; nt++) {
            #pragma unroll
            for (int ks = 0; ks < 8; ks++) {
                uint4 vf = VF[(nt * 8 + ks) * 32 + lane];
                mma16816(o[nt], pha[ks], vf.x, vf.y);
                mma16816(o[nt], pla[ks], vf.x, vf.y);
                mma16816(o[nt], pha[ks], vf.z, vf.w);
            }
        }
    }

    // ---- epilogue: reduce row sums across the quad, divide, store ----
    rs0 += __shfl_xor_sync(0xffffffffu, rs0, 1);
    rs0 += __shfl_xor_sync(0xffffffffu, rs0, 2);
    rs1 += __shfl_xor_sync(0xffffffffu, rs1, 1);
    rs1 += __shfl_xor_sync(0xffffffffu, rs1, 2);
    const float inv0 = 1.0f / rs0;
    const float inv1 = 1.0f / rs1;

    float* orow0 = ot + (warp * 16 + g) * DIM + 2 * tig;
    float* orow1 = orow0 + 8 * DIM;
    #pragma unroll
    for (int nt = 0; nt < 8; nt++) {
        *(float2*)(orow0 + nt * 8) = make_float2(o[nt][0] * inv0, o[nt][1] * inv0);
        *(float2*)(orow1 + nt * 8) = make_float2(o[nt][2] * inv1, o[nt][3] * inv1);
    }
}

extern "C" void kernel_launch(void* const* d_in, const int* in_sizes, int n_in,
                              void* d_out, int out_size) {
    const float* q = (const float*)d_in[0];
    const float* k = (const float*)d_in[1];
    const float* v = (const float*)d_in[2];
    float* o = (float*)d_out;

    cudaFuncSetAttribute(sdpa_mma_kernel,
                         cudaFuncAttributeMaxDynamicSharedMemorySize, SM_BYTES);
    dim3 grid(S_LEN / BM, NHEADS);   // (16, 64)
    sdpa_mma_kernel<<<grid, NTH, SM_BYTES>>>(q, k, v, o);
}

// round 14
// speedup vs baseline: 1.1848x; 1.0424x over previous
#include <cuda_runtime.h>
#include <cuda_bf16.h>
#include <cstdint>

// Flash-style SDPA via portable mma.sync (bf16 HMMA), sm_103-safe PTX.
// B=4,H=16,S=2048,D=64 fp32. Split-bf16 3-term MMAs for both GEMMs.
// R10: double-buffered fragment smem; pack(t+1) is threaded BETWEEN tile t's
// MMA chains (GEMM1 -> packK -> softmax -> GEMM2 -> packV -> sync) so the
// pack/softmax scalar work executes while the tensor pipe drains HMMAs.
// Pack reads gmem directly (L2-resident across the 16 CTAs per head).

#define S_LEN   2048
#define NHEADS  64
#define DIM     64
#define BM      128
#define BN      128
#define NKT     (S_LEN / BN)   // 16
#define NTH     256

// smem: 2 buffers x (KF 2048 uint4 + VF 2048 uint4) = 128 KB
#define SM_BYTES (4 * 32768)

#define QSCALE (0.125f * 1.4426950408889634f)   // 1/sqrt(64) * log2(e)

__device__ __forceinline__ float ex2(float x) {
    float y;
    asm("ex2.approx.f32 %0, %1;" : "=f"(y) : "f"(x));
    return y;
}

__device__ __forceinline__ void split2(float a, float b, uint32_t& hi, uint32_t& lo) {
    __nv_bfloat162 h = __floats2bfloat162_rn(a, b);
    float ra = a - __bfloat162float(h.x);
    float rb = b - __bfloat162float(h.y);
    __nv_bfloat162 l = __floats2bfloat162_rn(ra, rb);
    hi = *reinterpret_cast<uint32_t*>(&h);
    lo = *reinterpret_cast<uint32_t*>(&l);
}

__device__ __forceinline__ void mma16816(float* c, const uint32_t* a,
                                         uint32_t b0, uint32_t b1) {
    asm volatile(
        "mma.sync.aligned.m16n8k16.row.col.f32.bf16.bf16.f32 "
        "{%0,%1,%2,%3}, {%4,%5,%6,%7}, {%8,%9}, {%0,%1,%2,%3};"
        : "+f"(c[0]), "+f"(c[1]), "+f"(c[2]), "+f"(c[3])
        : "r"(a[0]), "r"(a[1]), "r"(a[2]), "r"(a[3]), "r"(b0), "r"(b1));
}

__global__ __launch_bounds__(NTH, 1)
void sdpa_mma_kernel(const float* __restrict__ qg, const float* __restrict__ kg,
                     const float* __restrict__ vg, float* __restrict__ og) {
    extern __shared__ __align__(16) char smem[];
    uint4* const KB[2] = { (uint4*)smem,            (uint4*)(smem + 32768) };
    uint4* const VB[2] = { (uint4*)(smem + 65536),  (uint4*)(smem + 98304) };

    const int tid  = threadIdx.x;
    const int warp = tid >> 5;
    const int lane = tid & 31;
    const int g    = lane >> 2;
    const int tig  = lane & 3;

    const int head = blockIdx.y;
    const int mt   = blockIdx.x;

    const float* qt = qg + ((size_t)head * S_LEN + (size_t)mt * BM) * DIM;
    const float* kb = kg + (size_t)head * S_LEN * DIM;
    const float* vb = vg + (size_t)head * S_LEN * DIM;
    float*       ot = og + ((size_t)head * S_LEN + (size_t)mt * BM) * DIM;

    // decomposed pack indices (per-thread constants across iterations)
    const int kp_ln = tid & 31;            // lane part of pos for i-loop
    const int kp_gg = kp_ln >> 2, kp_tt = kp_ln & 3;

    // ---- packK(t, buf): K tile -> B-frag order uint4 (hi,hi,lo,lo) ----
    auto packK = [&](int t, uint4* KF) {
        const float* kt = kb + (size_t)t * BN * DIM;
        #pragma unroll
        for (int i = 0; i < 8; i++) {
            int pos = i * NTH + tid;
            int ks = (pos >> 5) & 3, nt = pos >> 7;
            const float* src = kt + (nt * 8 + kp_gg) * DIM + ks * 16 + 2 * kp_tt;
            float2 x0 = *(const float2*)src;
            float2 x1 = *(const float2*)(src + 8);
            uint32_t h0, l0, h1, l1;
            split2(x0.x, x0.y, h0, l0);
            split2(x1.x, x1.y, h1, l1);
            KF[pos] = make_uint4(h0, h1, l0, l1);
        }
    };
    // ---- packV(t, buf): V tile -> B-frag order ----
    auto packV = [&](int t, uint4* VF) {
        const float* vt = vb + (size_t)t * BN * DIM;
        #pragma unroll
        for (int i = 0; i < 8; i++) {
            int pos = i * NTH + tid;
            int ks = (pos >> 5) & 7, nt = pos >> 8;
            const float* src = vt + (ks * 16 + 2 * kp_tt) * DIM + nt * 8 + kp_gg;
            float y0 = src[0];
            float y1 = src[DIM];
            float y2 = src[8 * DIM];
            float y3 = src[9 * DIM];
            uint32_t h0, l0, h1, l1;
            split2(y0, y1, h0, l0);
            split2(y2, y3, h1, l1);
            VF[pos] = make_uint4(h0, h1, l0, l1);
        }
    };

    // ---- Q fragments, register-resident, scale = 1/sqrt(D) * log2(e) ----
    uint32_t qh[4][4], ql[4][4];
    {
        const float* qr = qt + (warp * 16 + g) * DIM + 2 * tig;
        #pragma unroll
        for (int ks = 0; ks < 4; ks++) {
            float2 u0 = *(const float2*)(qr + ks * 16);
            float2 u1 = *(const float2*)(qr + ks * 16 + 8);
            float2 u2 = *(const float2*)(qr + ks * 16 + 8 * DIM);
            float2 u3 = *(const float2*)(qr + ks * 16 + 8 * DIM + 8);
            split2(QSCALE * u0.x, QSCALE * u0.y, qh[ks][0], ql[ks][0]);
            split2(QSCALE * u2.x, QSCALE * u2.y, qh[ks][1], ql[ks][1]);
            split2(QSCALE * u1.x, QSCALE * u1.y, qh[ks][2], ql[ks][2]);
            split2(QSCALE * u3.x, QSCALE * u3.y, qh[ks][3], ql[ks][3]);
        }
    }

    // ---- prologue: pack tile 0 into buffer 0 ----
    packK(0, KB[0]);
    packV(0, VB[0]);
    __syncthreads();

    float o[8][4];
    #pragma unroll
    for (int i = 0; i < 8; i++)
        #pragma unroll
        for (int j = 0; j < 4; j++) o[i][j] = 0.0f;
    float rs0 = 0.0f, rs1 = 0.0f;

    for (int t = 0; t < NKT; t++) {
        const int cur = t & 1, nxt = cur ^ 1;
        const uint4* KF = KB[cur];
        const uint4* VF = VB[cur];

        // ---- GEMM1: S = Qh Kh + Qh Kl + Ql Kh ----
        float s[16][4];
        #pragma unroll
        for (int nt = 0; nt < 16; nt++) {
            s[nt][0] = s[nt][1] = s[nt][2] = s[nt][3] = 0.0f;
            #pragma unroll
            for (int ks = 0; ks < 4; ks++) {
                uint4 kf = KF[(nt * 4 + ks) * 32 + lane];
                mma16816(s[nt], qh[ks], kf.x, kf.y);
                mma16816(s[nt], qh[ks], kf.z, kf.w);
                mma16816(s[nt], ql[ks], kf.x, kf.y);
            }
        }

        // ---- pack K of tile t+1 (overlaps GEMM1 tensor drain) ----
        if (t + 1 < NKT) packK(t + 1, KB[nxt]);

        // ---- 2^s + rowsum + split to GEMM2 A-frags (registers) ----
        uint32_t pha[8][4], pla[8][4];
        #pragma unroll
        for (int s8 = 0; s8 < 8; s8++) {
            float p00 = ex2(s[2 * s8][0]),     p01 = ex2(s[2 * s8][1]);
            float p02 = ex2(s[2 * s8][2]),     p03 = ex2(s[2 * s8][3]);
            float p10 = ex2(s[2 * s8 + 1][0]), p11 = ex2(s[2 * s8 + 1][1]);
            float p12 = ex2(s[2 * s8 + 1][2]), p13 = ex2(s[2 * s8 + 1][3]);
            rs0 += (p00 + p01) + (p10 + p11);
            rs1 += (p02 + p03) + (p12 + p13);
            split2(p00, p01, pha[s8][0], pla[s8][0]);
            split2(p02, p03, pha[s8][1], pla[s8][1]);
            split2(p10, p11, pha[s8][2], pla[s8][2]);
            split2(p12, p13, pha[s8][3], pla[s8][3]);
        }

        // ---- GEMM2: O += Ph Vh + Pl Vh + Ph Vl ----
        #pragma unroll
        for (int nt = 0; nt < 8; nt++) {
            #pragma unroll
            for (int ks = 0; ks < 8; ks++) {
                uint4 vf = VF[(nt * 8 + ks) * 32 + lane];
                mma16816(o[nt], pha[ks], vf.x, vf.y);
                mma16816(o[nt], pla[ks], vf.x, vf.y);
                mma16816(o[nt], pha[ks], vf.z, vf.w);
            }
        }

        // ---- pack V of tile t+1 (overlaps GEMM2 tensor drain) ----
        if (t + 1 < NKT) packV(t + 1, VB[nxt]);

        __syncthreads();   // frag[nxt] complete; frag[cur] free for t+2 writes
    }

    // ---- epilogue: reduce row sums across the quad, divide, store ----
    rs0 += __shfl_xor_sync(0xffffffffu, rs0, 1);
    rs0 += __shfl_xor_sync(0xffffffffu, rs0, 2);
    rs1 += __shfl_xor_sync(0xffffffffu, rs1, 1);
    rs1 += __shfl_xor_sync(0xffffffffu, rs1, 2);
    const float inv0 = 1.0f / rs0;
    const float inv1 = 1.0f / rs1;

    float* orow0 = ot + (warp * 16 + g) * DIM + 2 * tig;
    float* orow1 = orow0 + 8 * DIM;
    #pragma unroll
    for (int nt = 0; nt < 8; nt++) {
        *(float2*)(orow0 + nt * 8) = make_float2(o[nt][0] * inv0, o[nt][1] * inv0);
        *(float2*)(orow1 + nt * 8) = make_float2(o[nt][2] * inv1, o[nt][3] * inv1);
    }
}

extern "C" void kernel_launch(void* const* d_in, const int* in_sizes, int n_in,
                              void* d_out, int out_size) {
    const float* q = (const float*)d_in[0];
    const float* k = (const float*)d_in[1];
    const float* v = (const float*)d_in[2];
    float* o = (float*)d_out;

    cudaFuncSetAttribute(sdpa_mma_kernel,
                         cudaFuncAttributeMaxDynamicSharedMemorySize, SM_BYTES);
    dim3 grid(S_LEN / BM, NHEADS);   // (16, 64)
    sdpa_mma_kernel<<<grid, NTH, SM_BYTES>>>(q, k, v, o);
}

// round 15
// speedup vs baseline: 1.4609x; 1.2330x over previous
#include <cuda_runtime.h>
#include <cuda_bf16.h>
#include <cstdint>

// Flash-style SDPA via portable mma.sync (bf16 HMMA), sm_103-safe PTX.
// B=4,H=16,S=2048,D=64 fp32. Split-bf16 3-term MMAs for both GEMMs.
// R15: K/V split+pack hoisted into a ONE-SHOT pre-pass kernel (it was being
// redone 16x redundantly by the 16 CTAs of each head). Main kernel streams
// prepacked fragments with cp.async (distance-2 double buffer); per-tile
// scalar work is softmax only.

#define S_LEN   2048
#define NHEADS  64
#define DIM     64
#define BM      128
#define BN      128
#define NKT     (S_LEN / BN)   // 16
#define NTH     256
#define NPOS    2048           // uint4 fragments per (tile, tensor)

#define QSCALE (0.125f * 1.4426950408889634f)   // 1/sqrt(64) * log2(e)

// prepacked fragment scratch: [head][tile][pos], 32 MB each
__device__ uint4 KFg[(size_t)NHEADS * NKT * NPOS];
__device__ uint4 VFg[(size_t)NHEADS * NKT * NPOS];

__device__ __forceinline__ float ex2(float x) {
    float y;
    asm("ex2.approx.f32 %0, %1;" : "=f"(y) : "f"(x));
    return y;
}

__device__ __forceinline__ uint32_t smem_u32(const void* p) {
    uint32_t a;
    asm("{ .reg .u64 t; cvta.to.shared.u64 t, %1; cvt.u32.u64 %0, t; }"
        : "=r"(a) : "l"(p));
    return a;
}

__device__ __forceinline__ void cp16(uint32_t saddr, const void* gaddr) {
    asm volatile("cp.async.ca.shared.global [%0], [%1], 16;"
                 :: "r"(saddr), "l"(gaddr) : "memory");
}
#define CP_COMMIT() asm volatile("cp.async.commit_group;" ::: "memory")
#define CP_WAIT0()  asm volatile("cp.async.wait_group 0;" ::: "memory")
#define CP_WAIT1()  asm volatile("cp.async.wait_group 1;" ::: "memory")

__device__ __forceinline__ void split2(float a, float b, uint32_t& hi, uint32_t& lo) {
    __nv_bfloat162 h = __floats2bfloat162_rn(a, b);
    float ra = a - __bfloat162float(h.x);
    float rb = b - __bfloat162float(h.y);
    __nv_bfloat162 l = __floats2bfloat162_rn(ra, rb);
    hi = *reinterpret_cast<uint32_t*>(&h);
    lo = *reinterpret_cast<uint32_t*>(&l);
}

__device__ __forceinline__ void mma16816(float* c, const uint32_t* a,
                                         uint32_t b0, uint32_t b1) {
    asm volatile(
        "mma.sync.aligned.m16n8k16.row.col.f32.bf16.bf16.f32 "
        "{%0,%1,%2,%3}, {%4,%5,%6,%7}, {%8,%9}, {%0,%1,%2,%3};"
        : "+f"(c[0]), "+f"(c[1]), "+f"(c[2]), "+f"(c[3])
        : "r"(a[0]), "r"(a[1]), "r"(a[2]), "r"(a[3]), "r"(b0), "r"(b1));
}

// ---- pre-pass: K,V (fp32) -> split-bf16 fragment layout in gmem ----
__global__ __launch_bounds__(NTH)
void pack_kv_kernel(const float* __restrict__ kg, const float* __restrict__ vg) {
    const int head = blockIdx.y;
    const int t    = blockIdx.x;
    const int tid  = threadIdx.x;
    const int ln = tid & 31, gg = ln >> 2, tt = ln & 3;

    const float* kt = kg + ((size_t)head * S_LEN + (size_t)t * BN) * DIM;
    const float* vt = vg + ((size_t)head * S_LEN + (size_t)t * BN) * DIM;
    uint4* KF = KFg + ((size_t)head * NKT + t) * NPOS;
    uint4* VF = VFg + ((size_t)head * NKT + t) * NPOS;

    // K frag: pos=(nt*4+ks)*32+lane, B-frag of m16n8k16 (row-major K rows)
    #pragma unroll
    for (int i = 0; i < 8; i++) {
        int pos = i * NTH + tid;
        int ks = (pos >> 5) & 3, nt = pos >> 7;
        const float* src = kt + (nt * 8 + gg) * DIM + ks * 16 + 2 * tt;
        float2 x0 = *(const float2*)src;
        float2 x1 = *(const float2*)(src + 8);
        uint32_t h0, l0, h1, l1;
        split2(x0.x, x0.y, h0, l0);
        split2(x1.x, x1.y, h1, l1);
        KF[pos] = make_uint4(h0, h1, l0, l1);
    }
    // V frag: pos=(nt*8+ks)*32+lane, B[k=key][n=dim]
    #pragma unroll
    for (int i = 0; i < 8; i++) {
        int pos = i * NTH + tid;
        int ks = (pos >> 5) & 7, nt = pos >> 8;
        const float* src = vt + (ks * 16 + 2 * tt) * DIM + nt * 8 + gg;
        float y0 = src[0];
        float y1 = src[DIM];
        float y2 = src[8 * DIM];
        float y3 = src[9 * DIM];
        uint32_t h0, l0, h1, l1;
        split2(y0, y1, h0, l0);
        split2(y2, y3, h1, l1);
        VF[pos] = make_uint4(h0, h1, l0, l1);
    }
}

// ---- main kernel ----
// smem: 2 buffers x (KF 32KB + VF 32KB) = 128 KB
#define SM_BYTES (2 * 65536)

__global__ __launch_bounds__(NTH, 1)
void sdpa_mma_kernel(const float* __restrict__ qg, float* __restrict__ og) {
    extern __shared__ __align__(16) char smem[];

    const int tid  = threadIdx.x;
    const int warp = tid >> 5;
    const int lane = tid & 31;
    const int g    = lane >> 2;
    const int tig  = lane & 3;

    const int head = blockIdx.y;
    const int mt   = blockIdx.x;

    const float* qt = qg + ((size_t)head * S_LEN + (size_t)mt * BM) * DIM;
    float*       ot = og + ((size_t)head * S_LEN + (size_t)mt * BM) * DIM;

    const uint32_t sb = smem_u32(smem);
    const uint4* kfh = KFg + (size_t)head * NKT * NPOS;
    const uint4* vfh = VFg + (size_t)head * NKT * NPOS;

    // stage tile t's prepacked fragments into buffer buf
    auto stage = [&](int t, int buf) {
        const uint4* ks = kfh + (size_t)t * NPOS;
        const uint4* vs = vfh + (size_t)t * NPOS;
        uint32_t db = sb + (uint32_t)buf * 65536u;
        #pragma unroll
        for (int i = 0; i < 8; i++) {
            int pos = i * NTH + tid;
            cp16(db + (uint32_t)pos * 16u, ks + pos);
        }
        #pragma unroll
        for (int i = 0; i < 8; i++) {
            int pos = i * NTH + tid;
            cp16(db + 32768u + (uint32_t)pos * 16u, vs + pos);
        }
        CP_COMMIT();
    };

    stage(0, 0);
    stage(1, 1);

    // ---- Q fragments, register-resident, scale = 1/sqrt(D) * log2(e) ----
    uint32_t qh[4][4], ql[4][4];
    {
        const float* qr = qt + (warp * 16 + g) * DIM + 2 * tig;
        #pragma unroll
        for (int ks = 0; ks < 4; ks++) {
            float2 u0 = *(const float2*)(qr + ks * 16);
            float2 u1 = *(const float2*)(qr + ks * 16 + 8);
            float2 u2 = *(const float2*)(qr + ks * 16 + 8 * DIM);
            float2 u3 = *(const float2*)(qr + ks * 16 + 8 * DIM + 8);
            split2(QSCALE * u0.x, QSCALE * u0.y, qh[ks][0], ql[ks][0]);
            split2(QSCALE * u2.x, QSCALE * u2.y, qh[ks][1], ql[ks][1]);
            split2(QSCALE * u1.x, QSCALE * u1.y, qh[ks][2], ql[ks][2]);
            split2(QSCALE * u3.x, QSCALE * u3.y, qh[ks][3], ql[ks][3]);
        }
    }

    float o[8][4];
    #pragma unroll
    for (int i = 0; i < 8; i++)
        #pragma unroll
        for (int j = 0; j < 4; j++) o[i][j] = 0.0f;
    float rs0 = 0.0f, rs1 = 0.0f;

    for (int t = 0; t < NKT; t++) {
        if (t == NKT - 1) { CP_WAIT0(); } else { CP_WAIT1(); }   // tile t landed
        __syncthreads();

        const uint4* KF = (const uint4*)(smem + (t & 1) * 65536);
        const uint4* VF = KF + NPOS;

        // ---- GEMM1: S = Qh Kh + Qh Kl + Ql Kh ----
        float s[16][4];
        #pragma unroll
        for (int nt = 0; nt < 16; nt++) {
            s[nt][0] = s[nt][1] = s[nt][2] = s[nt][3] = 0.0f;
            #pragma unroll
            for (int ks = 0; ks < 4; ks++) {
                uint4 kf = KF[(nt * 4 + ks) * 32 + lane];
                mma16816(s[nt], qh[ks], kf.x, kf.y);
                mma16816(s[nt], qh[ks], kf.z, kf.w);
                mma16816(s[nt], ql[ks], kf.x, kf.y);
            }
        }

        // ---- 2^s + rowsum + split to GEMM2 A-frags (registers) ----
        uint32_t pha[8][4], pla[8][4];
        #pragma unroll
        for (int s8 = 0; s8 < 8; s8++) {
            float p00 = ex2(s[2 * s8][0]),     p01 = ex2(s[2 * s8][1]);
            float p02 = ex2(s[2 * s8][2]),     p03 = ex2(s[2 * s8][3]);
            float p10 = ex2(s[2 * s8 + 1][0]), p11 = ex2(s[2 * s8 + 1][1]);
            float p12 = ex2(s[2 * s8 + 1][2]), p13 = ex2(s[2 * s8 + 1][3]);
            rs0 += (p00 + p01) + (p10 + p11);
            rs1 += (p02 + p03) + (p12 + p13);
            split2(p00, p01, pha[s8][0], pla[s8][0]);
            split2(p02, p03, pha[s8][1], pla[s8][1]);
            split2(p10, p11, pha[s8][2], pla[s8][2]);
            split2(p12, p13, pha[s8][3], pla[s8][3]);
        }

        // ---- GEMM2: O += Ph Vh + Pl Vh + Ph Vl ----
        #pragma unroll
        for (int nt = 0; nt < 8; nt++) {
            #pragma unroll
            for (int ks = 0; ks < 8; ks++) {
                uint4 vf = VF[(nt * 8 + ks) * 32 + lane];
                mma16816(o[nt], pha[ks], vf.x, vf.y);
                mma16816(o[nt], pla[ks], vf.x, vf.y);
                mma16816(o[nt], pha[ks], vf.z, vf.w);
            }
        }

        __syncthreads();   // buffer (t&1) fully consumed by all warps
        if (t + 2 < NKT) stage(t + 2, t & 1);
    }

    // ---- epilogue: reduce row sums across the quad, divide, store ----
    rs0 += __shfl_xor_sync(0xffffffffu, rs0, 1);
    rs0 += __shfl_xor_sync(0xffffffffu, rs0, 2);
    rs1 += __shfl_xor_sync(0xffffffffu, rs1, 1);
    rs1 += __shfl_xor_sync(0xffffffffu, rs1, 2);
    const float inv0 = 1.0f / rs0;
    const float inv1 = 1.0f / rs1;

    float* orow0 = ot + (warp * 16 + g) * DIM + 2 * tig;
    float* orow1 = orow0 + 8 * DIM;
    #pragma unroll
    for (int nt = 0; nt < 8; nt++) {
        *(float2*)(orow0 + nt * 8) = make_float2(o[nt][0] * inv0, o[nt][1] * inv0);
        *(float2*)(orow1 + nt * 8) = make_float2(o[nt][2] * inv1, o[nt][3] * inv1);
    }
}

extern "C" void kernel_launch(void* const* d_in, const int* in_sizes, int n_in,
                              void* d_out, int out_size) {
    const float* q = (const float*)d_in[0];
    const float* k = (const float*)d_in[1];
    const float* v = (const float*)d_in[2];
    float* o = (float*)d_out;

    cudaFuncSetAttribute(sdpa_mma_kernel,
                         cudaFuncAttributeMaxDynamicSharedMemorySize, SM_BYTES);

    dim3 pgrid(NKT, NHEADS);          // (16, 64)
    pack_kv_kernel<<<pgrid, NTH>>>(k, v);

    dim3 grid(S_LEN / BM, NHEADS);    // (16, 64)
    sdpa_mma_kernel<<<grid, NTH, SM_BYTES>>>(q, o);
}